// round 9
// baseline (speedup 1.0000x reference)
#include <cuda_runtime.h>
#include <cuda_fp16.h>
#include <stdint.h>
#include <math.h>

// ---------------- problem constants ----------------
#define BATCH 2
#define SEQ   1024
#define HDIM  2048
#define NH    16
#define NKV   4
#define HD    128
#define NEXP  8
#define IDIM  2048
#define TTOK  (BATCH*SEQ)          // 2048 tokens
#define QKVW  ((NH+2*NKV)*HD)      // 3072
#define SCALE 0.08838834764831845f // 128^-0.5
#define EPS_RMS 1e-5f
#define EPS_L2  1e-6f

// ---------------- scratch (device globals; no allocation allowed) ----------
__device__ float  g_qkv [TTOK*QKVW];
__device__ float  g_x2  [TTOK*HDIM];
__device__ float  g_h2  [TTOK*HDIM];
__device__ float  g_gus [TTOK*2*IDIM];
__device__ float  g_gur [TTOK*2*IDIM];

__device__ __half g_h16  [TTOK*HDIM];
__device__ __half g_q16  [TTOK*NH*HD];
__device__ __half g_k16  [TTOK*NKV*HD];
__device__ __half g_o16  [TTOK*NH*HD];
__device__ __half g_h2_16[TTOK*HDIM];
__device__ __half g_acs16[TTOK*IDIM];
__device__ __half g_acr16[TTOK*IDIM];

// fp16 k-major (transposed) weights
__device__ __half g_wqkvT [QKVW*HDIM];
__device__ __half g_woT   [HDIM*NH*HD];
__device__ __half g_wshguT[2*IDIM*HDIM];
__device__ __half g_wshdnT[HDIM*IDIM];
__device__ __half g_wguT  [(size_t)NEXP*2*IDIM*HDIM];
__device__ __half g_wdnT  [(size_t)NEXP*HDIM*IDIM];

__device__ int   g_cnt[NEXP];
__device__ int   g_off[NEXP];
__device__ int   g_tok_expert[TTOK];
__device__ int   g_tok_rank[TTOK];
__device__ float g_tok_scale[TTOK];
__device__ int   g_slot_tok[TTOK];

// ---------------- common PTX helpers ----------------
__device__ __forceinline__ void cp16(uint32_t dst, const void* src) {
    asm volatile("cp.async.ca.shared.global [%0], [%1], 16;" :: "r"(dst), "l"(src));
}
__device__ __forceinline__ uint32_t f2tf32(float f) {
    uint32_t u;
    asm("cvt.rna.tf32.f32 %0, %1;" : "=r"(u) : "f"(f));
    return u;
}
__device__ __forceinline__ void mma_tf32(float* c, const uint32_t* a, const uint32_t* b) {
    asm volatile(
        "mma.sync.aligned.m16n8k8.row.col.f32.tf32.tf32.f32 "
        "{%0,%1,%2,%3}, {%4,%5,%6,%7}, {%8,%9}, {%0,%1,%2,%3};"
        : "+f"(c[0]), "+f"(c[1]), "+f"(c[2]), "+f"(c[3])
        : "r"(a[0]), "r"(a[1]), "r"(a[2]), "r"(a[3]), "r"(b[0]), "r"(b[1]));
}
__device__ __forceinline__ void mma_f16(float* c, const uint32_t* a, const uint32_t* b) {
    asm volatile(
        "mma.sync.aligned.m16n8k16.row.col.f32.f16.f16.f32 "
        "{%0,%1,%2,%3}, {%4,%5,%6,%7}, {%8,%9}, {%0,%1,%2,%3};"
        : "+f"(c[0]), "+f"(c[1]), "+f"(c[2]), "+f"(c[3])
        : "r"(a[0]), "r"(a[1]), "r"(a[2]), "r"(a[3]), "r"(b[0]), "r"(b[1]));
}
__device__ __forceinline__ void ldsm_x4(uint32_t& r0, uint32_t& r1, uint32_t& r2, uint32_t& r3,
                                        uint32_t addr) {
    asm volatile("ldmatrix.sync.aligned.m8n8.x4.shared.b16 {%0,%1,%2,%3}, [%4];"
                 : "=r"(r0), "=r"(r1), "=r"(r2), "=r"(r3) : "r"(addr));
}

// ---------------- transpose + fp32 -> fp16 convert ----------------
__global__ __launch_bounds__(256)
void transpose_cvt_kernel(const float* __restrict__ in, __half* __restrict__ out,
                          int R, int C)
{
    __shared__ float t[32][33];
    size_t slab = (size_t)blockIdx.z * R * C;
    in  += slab;
    out += slab;
    int c0 = blockIdx.x * 32, r0 = blockIdx.y * 32;
    #pragma unroll
    for (int i = 0; i < 4; i++) {
        int r = r0 + threadIdx.y + i * 8;
        t[threadIdx.y + i * 8][threadIdx.x] = in[(size_t)r * C + c0 + threadIdx.x];
    }
    __syncthreads();
    #pragma unroll
    for (int i = 0; i < 4; i++) {
        int c = c0 + threadIdx.y + i * 8;
        out[(size_t)c * R + r0 + threadIdx.x] = __float2half(t[threadIdx.x][threadIdx.y + i * 8]);
    }
}

// ---------------- RMSNorm (fp16 out, optional fp32 out) ----------------
__global__ void rmsnorm_kernel(const float* __restrict__ x,
                               const float* __restrict__ w,
                               __half* __restrict__ out16,
                               float* __restrict__ out32)
{
    int t = blockIdx.x;
    const float* xr = x + (size_t)t * HDIM;
    float ss = 0.f;
    for (int i = threadIdx.x; i < HDIM; i += blockDim.x) {
        float v = xr[i];
        ss += v * v;
    }
    __shared__ float red[8];
    int lane = threadIdx.x & 31, wid = threadIdx.x >> 5;
    #pragma unroll
    for (int o = 16; o; o >>= 1) ss += __shfl_xor_sync(0xffffffffu, ss, o);
    if (lane == 0) red[wid] = ss;
    __syncthreads();
    if (wid == 0) {
        float v = (lane < (blockDim.x >> 5)) ? red[lane] : 0.f;
        #pragma unroll
        for (int o = 16; o; o >>= 1) v += __shfl_xor_sync(0xffffffffu, v, o);
        if (lane == 0) red[0] = v;
    }
    __syncthreads();
    float r = rsqrtf(red[0] / (float)HDIM + EPS_RMS);
    for (int i = threadIdx.x; i < HDIM; i += blockDim.x) {
        float v = xr[i] * r * w[i];
        out16[(size_t)t * HDIM + i] = __float2half(v);
        if (out32) out32[(size_t)t * HDIM + i] = v;
    }
}

// =====================================================================
// fp16 tensor-core GEMM with ldmatrix: C[M,N] = A[M,K] @ Bt[N,K]^T (+D)
// A, Bt fp16 k-major. CTA 128x128, K-tile 32, double-buffered cp.async,
// 128 threads = 4 warps (2m x 2n), warp tile 64x64, mma m16n8k16.
// Fragments loaded via ldmatrix.x4 (8 A + 8 B LDSM per warp per k-tile).
// modes: 0 plain(+D), 1 expert gate_up (gather+scale), 2 expert down (scatter)
// =====================================================================
#define AHS 40    // smem stride (halves): 32 + 8 pad
#define OP_BUF_BYTES (128*AHS*2)                 // 10240 per operand per stage
#define HG_SMEM (4*OP_BUF_BYTES)                 // 40960

__global__ __launch_bounds__(128)
void hgemm(int M, int N, int K,
           const __half* __restrict__ A,
           const __half* __restrict__ Bt, size_t b_expert_stride,
           float* __restrict__ C,
           const float* __restrict__ D,
           int mode)
{
    extern __shared__ char sm[];
    uint32_t asBase = (uint32_t)__cvta_generic_to_shared(sm);
    uint32_t bsBase = asBase + 2 * OP_BUF_BYTES;

    int crow = blockIdx.y * 128;
    int ccol = blockIdx.x * 128;
    int cnt = M, off = 0;
    if (mode) {
        int e = blockIdx.z;
        cnt = g_cnt[e];
        off = g_off[e];
        Bt += (size_t)e * b_expert_stride;
        if (crow >= cnt) return;
    }

    const int tid = threadIdx.x;
    const int warp = tid >> 5, lane = tid & 31;
    const int g = lane >> 2, tig = lane & 3;
    const int wm = (warp >> 1) * 64;
    const int wn = (warp & 1) * 64;

    // staging: per stage 128 rows x 4 chunks(16B) each operand -> 4/thread
    const __half* a_src[4];
    const __half* b_src[4];
    uint32_t st_off[4];
    #pragma unroll
    for (int i = 0; i < 4; i++) {
        int idx = tid + i * 128;
        int r = idx >> 2, c8 = (idx & 3) * 8;
        int gr = crow + r;
        int arow;
        if (mode == 1)      arow = g_slot_tok[off + (gr < cnt ? gr : cnt - 1)];
        else if (mode == 2) arow = off + (gr < cnt ? gr : cnt - 1);
        else                arow = gr;
        a_src[i] = A + (size_t)arow * K + c8;
        b_src[i] = Bt + (size_t)(ccol + r) * K + c8;
        st_off[i] = (uint32_t)((r * AHS + c8) * 2);
    }

    // ldmatrix per-lane fragment offsets
    int lr8 = lane & 7, seg1 = (lane >> 3) & 1, seg2 = lane >> 4;
    uint32_t a_frag = (uint32_t)(((wm + lr8 + seg1 * 8) * AHS + seg2 * 8) * 2);
    uint32_t b_frag = (uint32_t)(((wn + lr8 + seg1 * 8) * AHS + seg2 * 8) * 2);

    float acc[4][8][4];
    #pragma unroll
    for (int mt = 0; mt < 4; mt++)
        #pragma unroll
        for (int nt = 0; nt < 8; nt++)
            #pragma unroll
            for (int r = 0; r < 4; r++) acc[mt][nt][r] = 0.f;

    const int KT = K / 32;

    #pragma unroll
    for (int i = 0; i < 4; i++) {
        cp16(asBase + st_off[i], a_src[i]);
        cp16(bsBase + st_off[i], b_src[i]);
    }
    asm volatile("cp.async.commit_group;");

    for (int kt = 0; kt < KT; kt++) {
        int buf = kt & 1;
        if (kt + 1 < KT) {
            int k0 = (kt + 1) * 32;
            int nbuf = buf ^ 1;
            #pragma unroll
            for (int i = 0; i < 4; i++) {
                cp16(asBase + nbuf * OP_BUF_BYTES + st_off[i], a_src[i] + k0);
                cp16(bsBase + nbuf * OP_BUF_BYTES + st_off[i], b_src[i] + k0);
            }
            asm volatile("cp.async.commit_group;");
            asm volatile("cp.async.wait_group 1;");
        } else {
            asm volatile("cp.async.wait_group 0;");
        }
        __syncthreads();

        uint32_t aB = asBase + buf * OP_BUF_BYTES + a_frag;
        uint32_t bB = bsBase + buf * OP_BUF_BYTES + b_frag;

        uint32_t ua[2][4][4], ub[2][8][2];
        #pragma unroll
        for (int ks = 0; ks < 2; ks++) {
            uint32_t ka = aB + ks * 32;        // ks*16 halves
            uint32_t kb = bB + ks * 32;
            #pragma unroll
            for (int mt = 0; mt < 4; mt++)
                ldsm_x4(ua[ks][mt][0], ua[ks][mt][1], ua[ks][mt][2], ua[ks][mt][3],
                        ka + mt * (16 * AHS * 2));
            #pragma unroll
            for (int p = 0; p < 4; p++)
                ldsm_x4(ub[ks][2*p][0], ub[ks][2*p+1][0], ub[ks][2*p][1], ub[ks][2*p+1][1],
                        kb + p * (16 * AHS * 2));
        }
        #pragma unroll
        for (int ks = 0; ks < 2; ks++)
            #pragma unroll
            for (int mt = 0; mt < 4; mt++)
                #pragma unroll
                for (int nt = 0; nt < 8; nt++)
                    mma_f16(acc[mt][nt], ua[ks][mt], ub[ks][nt]);
        __syncthreads();
    }

    // ---------------- epilogue ----------------
    #pragma unroll
    for (int mt = 0; mt < 4; mt++) {
        #pragma unroll
        for (int h = 0; h < 2; h++) {
            int rl = wm + mt * 16 + g + h * 8;
            int gr = crow + rl;
            if (mode == 0) {
                size_t rbase = (size_t)gr * N;
                #pragma unroll
                for (int nt = 0; nt < 8; nt++) {
                    int c = ccol + wn + nt * 8 + tig * 2;
                    float v0 = acc[mt][nt][h * 2 + 0];
                    float v1 = acc[mt][nt][h * 2 + 1];
                    if (D) {
                        float2 dv = *(const float2*)(D + rbase + c);
                        v0 += dv.x; v1 += dv.y;
                    }
                    *(float2*)(C + rbase + c) = make_float2(v0, v1);
                }
            } else if (mode == 1) {
                if (gr < cnt) {
                    int slot = off + gr;
                    float s = g_tok_scale[g_slot_tok[slot]];
                    size_t rbase = (size_t)slot * N;
                    #pragma unroll
                    for (int nt = 0; nt < 8; nt++) {
                        int c = ccol + wn + nt * 8 + tig * 2;
                        *(float2*)(C + rbase + c) =
                            make_float2(s * acc[mt][nt][h * 2 + 0],
                                        s * acc[mt][nt][h * 2 + 1]);
                    }
                }
            } else {
                if (gr < cnt) {
                    int tok = g_slot_tok[off + gr];
                    size_t rbase = (size_t)tok * N;
                    #pragma unroll
                    for (int nt = 0; nt < 8; nt++) {
                        int c = ccol + wn + nt * 8 + tig * 2;
                        float2* cp = (float2*)(C + rbase + c);
                        float2 cv = *cp;
                        cv.x += acc[mt][nt][h * 2 + 0];
                        cv.y += acc[mt][nt][h * 2 + 1];
                        *cp = cv;
                    }
                }
            }
        }
    }
}

// ---------------- RoPE + L2-norm for q & k -> fp16 ----------------
__global__ void rope_l2_kernel(const float* __restrict__ qkv,
                               const float* __restrict__ freqs,
                               __half* __restrict__ qout,
                               __half* __restrict__ kout)
{
    int t = blockIdx.x;
    int lane = threadIdx.x & 31, w = threadIdx.x >> 5;
    int hh = blockIdx.y * 4 + w;
    int s = t & (SEQ - 1);

    const float* src;
    __half* dst;
    if (hh < NH) {
        src = qkv + (size_t)t * QKVW + hh * HD;
        dst = qout + (size_t)t * NH * HD + hh * HD;
    } else {
        int kv = hh - NH;
        src = qkv + (size_t)t * QKVW + NH * HD + kv * HD;
        dst = kout + (size_t)t * NKV * HD + kv * HD;
    }
    float4 xv = *(const float4*)(src + lane * 4);
    float4 fv = *(const float4*)(freqs + (size_t)s * HD + lane * 4);
    float o0 = xv.x * fv.x - xv.y * fv.y;
    float o1 = xv.x * fv.y + xv.y * fv.x;
    float o2 = xv.z * fv.z - xv.w * fv.w;
    float o3 = xv.z * fv.w + xv.w * fv.z;
    float ss = o0*o0 + o1*o1 + o2*o2 + o3*o3;
    #pragma unroll
    for (int o = 16; o; o >>= 1) ss += __shfl_xor_sync(0xffffffffu, ss, o);
    float r = rsqrtf(ss / (float)HD + EPS_L2);
    __half2 p0 = __floats2half2_rn(o0 * r, o1 * r);
    __half2 p1 = __floats2half2_rn(o2 * r, o3 * r);
    *(__half2*)(dst + lane * 4)     = p0;
    *(__half2*)(dst + lane * 4 + 2) = p1;
}

// =====================================================================
// flash attention: fp16 S-path (Q,K fp16 mma), tf32 P@V. 64 q rows/block.
// =====================================================================
#define KH_STRIDE 136   // halves
#define VS_STRIDE 136   // floats
#define P_STRIDE  68    // floats
#define FA_SMEM   (64*KH_STRIDE*2 + 64*VS_STRIDE*4 + 64*P_STRIDE*4)

__global__ __launch_bounds__(128)
void flash_attn_kernel(const __half* __restrict__ q,
                       const __half* __restrict__ k,
                       const float* __restrict__ qkv,
                       __half* __restrict__ o)
{
    extern __shared__ char fsm[];
    __half* Ks = (__half*)fsm;                         // [64][KH_STRIDE]
    float*  Vs = (float*)(fsm + 64 * KH_STRIDE * 2);   // [64][VS_STRIDE]
    float*  Ps = Vs + 64 * VS_STRIDE;                  // [64][P_STRIDE]

    int bh = blockIdx.x;
    int b = bh >> 4, h = bh & 15;
    int kvh = h >> 2;
    int q0 = blockIdx.y * 64;

    int tid = threadIdx.x, warp = tid >> 5, lane = tid & 31;
    int g = lane >> 2, tig = lane & 3;

    int qr0 = q0 + warp * 16 + g;
    int qr1 = qr0 + 8;
    const __half* qb0 = q + ((size_t)(b * SEQ + qr0) * NH + h) * HD;
    const __half* qb1 = q + ((size_t)(b * SEQ + qr1) * NH + h) * HD;
    uint32_t qa[8][4];
    #pragma unroll
    for (int ks = 0; ks < 8; ks++) {
        int c = ks * 16 + tig * 2;
        qa[ks][0] = *(const uint32_t*)&qb0[c];
        qa[ks][1] = *(const uint32_t*)&qb1[c];
        qa[ks][2] = *(const uint32_t*)&qb0[c + 8];
        qa[ks][3] = *(const uint32_t*)&qb1[c + 8];
    }

    float oacc[16][4];
    #pragma unroll
    for (int dt = 0; dt < 16; dt++)
        #pragma unroll
        for (int r = 0; r < 4; r++) oacc[dt][r] = 0.f;
    float m0 = -1e30f, m1 = -1e30f, l0 = 0.f, l1 = 0.f;

    uint32_t ksb = (uint32_t)__cvta_generic_to_shared(Ks);
    uint32_t vsb = (uint32_t)__cvta_generic_to_shared(Vs);

    const int ktiles = blockIdx.y + 1;
    for (int kt = 0; kt < ktiles; kt++) {
        const __half* kptr = k + ((size_t)(b * SEQ + kt * 64) * NKV + kvh) * HD;
        const float*  vptr = qkv + (size_t)(b * SEQ + kt * 64) * QKVW + (NH + NKV) * HD + kvh * HD;
        #pragma unroll
        for (int it = 0; it < 8; it++) {
            int idx = tid + it * 128;
            int r = idx >> 4, c = (idx & 15) * 8;
            cp16(ksb + (uint32_t)(r * KH_STRIDE + c) * 2, kptr + (size_t)r * (NKV * HD) + c);
        }
        #pragma unroll
        for (int it = 0; it < 16; it++) {
            int idx = tid + it * 128;
            int r = idx >> 5, c = (idx & 31) * 4;
            cp16(vsb + (uint32_t)(r * VS_STRIDE + c) * 4, vptr + (size_t)r * QKVW + c);
        }
        asm volatile("cp.async.commit_group;");
        asm volatile("cp.async.wait_group 0;");
        __syncthreads();

        float sacc[8][4];
        #pragma unroll
        for (int nt = 0; nt < 8; nt++)
            #pragma unroll
            for (int r = 0; r < 4; r++) sacc[nt][r] = 0.f;

        #pragma unroll
        for (int ks = 0; ks < 8; ks++) {
            int kb = ks * 16 + tig * 2;
            uint32_t ub[8][2];
            #pragma unroll
            for (int nt = 0; nt < 8; nt++) {
                int kr = nt * 8 + g;
                ub[nt][0] = *(const uint32_t*)&Ks[kr * KH_STRIDE + kb];
                ub[nt][1] = *(const uint32_t*)&Ks[kr * KH_STRIDE + kb + 8];
            }
            #pragma unroll
            for (int nt = 0; nt < 8; nt++)
                mma_f16(sacc[nt], qa[ks], ub[nt]);
        }

        bool diag = (kt == ktiles - 1);
        float rmax0 = -1e30f, rmax1 = -1e30f;
        #pragma unroll
        for (int nt = 0; nt < 8; nt++) {
            int c0 = kt * 64 + nt * 8 + tig * 2;
            float s0 = sacc[nt][0] * SCALE;
            float s1 = sacc[nt][1] * SCALE;
            float s2 = sacc[nt][2] * SCALE;
            float s3 = sacc[nt][3] * SCALE;
            if (diag) {
                if (c0 > qr0)     s0 = -1e30f;
                if (c0 + 1 > qr0) s1 = -1e30f;
                if (c0 > qr1)     s2 = -1e30f;
                if (c0 + 1 > qr1) s3 = -1e30f;
            }
            sacc[nt][0] = s0; sacc[nt][1] = s1;
            sacc[nt][2] = s2; sacc[nt][3] = s3;
            rmax0 = fmaxf(rmax0, fmaxf(s0, s1));
            rmax1 = fmaxf(rmax1, fmaxf(s2, s3));
        }
        #pragma unroll
        for (int off = 1; off <= 2; off <<= 1) {
            rmax0 = fmaxf(rmax0, __shfl_xor_sync(0xffffffffu, rmax0, off));
            rmax1 = fmaxf(rmax1, __shfl_xor_sync(0xffffffffu, rmax1, off));
        }
        float mn0 = fmaxf(m0, rmax0);
        float mn1 = fmaxf(m1, rmax1);
        float corr0 = __expf(m0 - mn0);
        float corr1 = __expf(m1 - mn1);
        m0 = mn0; m1 = mn1;

        float psum0 = 0.f, psum1 = 0.f;
        #pragma unroll
        for (int nt = 0; nt < 8; nt++) {
            float p0 = __expf(sacc[nt][0] - mn0);
            float p1 = __expf(sacc[nt][1] - mn0);
            float p2 = __expf(sacc[nt][2] - mn1);
            float p3 = __expf(sacc[nt][3] - mn1);
            psum0 += p0 + p1;
            psum1 += p2 + p3;
            int c = nt * 8 + tig * 2;
            *(float2*)&Ps[(warp * 16 + g) * P_STRIDE + c]     = make_float2(p0, p1);
            *(float2*)&Ps[(warp * 16 + g + 8) * P_STRIDE + c] = make_float2(p2, p3);
        }
        #pragma unroll
        for (int off = 1; off <= 2; off <<= 1) {
            psum0 += __shfl_xor_sync(0xffffffffu, psum0, off);
            psum1 += __shfl_xor_sync(0xffffffffu, psum1, off);
        }
        l0 = l0 * corr0 + psum0;
        l1 = l1 * corr1 + psum1;

        #pragma unroll
        for (int dt = 0; dt < 16; dt++) {
            oacc[dt][0] *= corr0; oacc[dt][1] *= corr0;
            oacc[dt][2] *= corr1; oacc[dt][3] *= corr1;
        }
        __syncwarp();

        #pragma unroll
        for (int ks = 0; ks < 8; ks++) {
            int k8 = ks * 8;
            uint32_t pa[4];
            pa[0] = f2tf32(Ps[(warp * 16 + g) * P_STRIDE + k8 + tig]);
            pa[1] = f2tf32(Ps[(warp * 16 + g + 8) * P_STRIDE + k8 + tig]);
            pa[2] = f2tf32(Ps[(warp * 16 + g) * P_STRIDE + k8 + tig + 4]);
            pa[3] = f2tf32(Ps[(warp * 16 + g + 8) * P_STRIDE + k8 + tig + 4]);
            #pragma unroll
            for (int dt = 0; dt < 16; dt++) {
                uint32_t vb[2];
                vb[0] = f2tf32(Vs[(k8 + tig) * VS_STRIDE + dt * 8 + g]);
                vb[1] = f2tf32(Vs[(k8 + tig + 4) * VS_STRIDE + dt * 8 + g]);
                mma_tf32(oacc[dt], pa, vb);
            }
        }
        __syncthreads();
    }

    float inv0 = 1.f / l0, inv1 = 1.f / l1;
    __half* ob0 = o + ((size_t)(b * SEQ + qr0) * NH + h) * HD;
    __half* ob1 = o + ((size_t)(b * SEQ + qr1) * NH + h) * HD;
    #pragma unroll
    for (int dt = 0; dt < 16; dt++) {
        int d = dt * 8 + tig * 2;
        *(__half2*)(ob0 + d) = __floats2half2_rn(oacc[dt][0] * inv0, oacc[dt][1] * inv0);
        *(__half2*)(ob1 + d) = __floats2half2_rn(oacc[dt][2] * inv1, oacc[dt][3] * inv1);
    }
}

// ---------------- router ----------------
__global__ void zero_cnt_kernel()
{
    if (threadIdx.x < NEXP) g_cnt[threadIdx.x] = 0;
}

__global__ void router_kernel(const float* __restrict__ h2,
                              const float* __restrict__ wr)
{
    int t = blockIdx.x;
    const float* hrow = h2 + (size_t)t * HDIM;
    float l[NEXP];
    #pragma unroll
    for (int e = 0; e < NEXP; e++) l[e] = 0.f;
    for (int kk = threadIdx.x; kk < HDIM; kk += blockDim.x) {
        float hv = hrow[kk];
        const float* wrow = wr + (size_t)kk * NEXP;
        #pragma unroll
        for (int e = 0; e < NEXP; e++) l[e] += hv * wrow[e];
    }
    __shared__ float sums[NEXP];
    if (threadIdx.x < NEXP) sums[threadIdx.x] = 0.f;
    __syncthreads();
    #pragma unroll
    for (int e = 0; e < NEXP; e++) {
        float v = l[e];
        #pragma unroll
        for (int o = 16; o; o >>= 1) v += __shfl_xor_sync(0xffffffffu, v, o);
        if ((threadIdx.x & 31) == 0) atomicAdd(&sums[e], v);
    }
    __syncthreads();
    if (threadIdx.x == 0) {
        int best = 0;
        float bv = sums[0];
        #pragma unroll
        for (int e = 1; e < NEXP; e++)
            if (sums[e] > bv) { bv = sums[e]; best = e; }
        g_tok_expert[t] = best;
        g_tok_scale[t]  = 1.f / (1.f + __expf(-bv));
        g_tok_rank[t]   = atomicAdd(&g_cnt[best], 1);
    }
}

__global__ void offsets_kernel()
{
    if (threadIdx.x == 0) {
        int run = 0;
        for (int e = 0; e < NEXP; e++) { g_off[e] = run; run += g_cnt[e]; }
    }
}

__global__ void slot_kernel()
{
    int t = blockIdx.x * blockDim.x + threadIdx.x;
    if (t < TTOK)
        g_slot_tok[g_off[g_tok_expert[t]] + g_tok_rank[t]] = t;
}

// ---------------- SiLU(g)*u -> fp16 ----------------
__global__ void silu_mul_kernel(const float* __restrict__ gu,
                                __half* __restrict__ out)
{
    int i = blockIdx.x * blockDim.x + threadIdx.x;
    if (i >= TTOK * IDIM) return;
    int row = i / IDIM, col = i - row * IDIM;
    float g = gu[(size_t)row * 2 * IDIM + col];
    float u = gu[(size_t)row * 2 * IDIM + IDIM + col];
    float sg = 1.f / (1.f + __expf(-g));
    out[i] = __float2half(u * g * sg);
}

// ---------------- launch ----------------
extern "C" void kernel_launch(void* const* d_in, const int* in_sizes, int n_in,
                              void* d_out, int out_size)
{
    const float* hidden   = (const float*)d_in[0];
    const float* freqs    = (const float*)d_in[1];
    const float* w_ln1    = (const float*)d_in[2];
    const float* w_qkv    = (const float*)d_in[3];
    const float* w_o      = (const float*)d_in[4];
    const float* w_ln2    = (const float*)d_in[5];
    const float* w_router = (const float*)d_in[6];
    const float* w_gu_e   = (const float*)d_in[7];
    const float* w_down_e = (const float*)d_in[8];
    const float* w_sh_gu  = (const float*)d_in[9];
    const float* w_sh_dn  = (const float*)d_in[10];
    float* out = (float*)d_out;

    float *p_qkv, *p_x2, *p_h2, *p_gus, *p_gur;
    __half *p_h16, *p_q16, *p_k16, *p_o16, *p_h2_16, *p_acs16, *p_acr16;
    __half *p_wqkvT, *p_woT, *p_wshguT, *p_wshdnT, *p_wguT, *p_wdnT;
    cudaGetSymbolAddress((void**)&p_qkv,   g_qkv);
    cudaGetSymbolAddress((void**)&p_x2,    g_x2);
    cudaGetSymbolAddress((void**)&p_h2,    g_h2);
    cudaGetSymbolAddress((void**)&p_gus,   g_gus);
    cudaGetSymbolAddress((void**)&p_gur,   g_gur);
    cudaGetSymbolAddress((void**)&p_h16,   g_h16);
    cudaGetSymbolAddress((void**)&p_q16,   g_q16);
    cudaGetSymbolAddress((void**)&p_k16,   g_k16);
    cudaGetSymbolAddress((void**)&p_o16,   g_o16);
    cudaGetSymbolAddress((void**)&p_h2_16, g_h2_16);
    cudaGetSymbolAddress((void**)&p_acs16, g_acs16);
    cudaGetSymbolAddress((void**)&p_acr16, g_acr16);
    cudaGetSymbolAddress((void**)&p_wqkvT, g_wqkvT);
    cudaGetSymbolAddress((void**)&p_woT,   g_woT);
    cudaGetSymbolAddress((void**)&p_wshguT,g_wshguT);
    cudaGetSymbolAddress((void**)&p_wshdnT,g_wshdnT);
    cudaGetSymbolAddress((void**)&p_wguT,  g_wguT);
    cudaGetSymbolAddress((void**)&p_wdnT,  g_wdnT);

    static int attr_set = 0;
    if (!attr_set) {
        cudaFuncSetAttribute(flash_attn_kernel,
                             cudaFuncAttributeMaxDynamicSharedMemorySize, FA_SMEM);
        cudaFuncSetAttribute(hgemm,
                             cudaFuncAttributeMaxDynamicSharedMemorySize, HG_SMEM);
        attr_set = 1;
    }

    dim3 tb(32, 8);
    // 0. weight transposes (fp32 [K][N] -> fp16 [N][K])
    transpose_cvt_kernel<<<dim3(QKVW/32,  HDIM/32), tb>>>(w_qkv,    p_wqkvT,  HDIM, QKVW);
    transpose_cvt_kernel<<<dim3(HDIM/32,  (NH*HD)/32), tb>>>(w_o,   p_woT,    NH*HD, HDIM);
    transpose_cvt_kernel<<<dim3((2*IDIM)/32, HDIM/32), tb>>>(w_sh_gu, p_wshguT, HDIM, 2*IDIM);
    transpose_cvt_kernel<<<dim3(HDIM/32,  IDIM/32), tb>>>(w_sh_dn,  p_wshdnT, IDIM, HDIM);
    transpose_cvt_kernel<<<dim3((2*IDIM)/32, HDIM/32, NEXP), tb>>>(w_gu_e,  p_wguT, HDIM, 2*IDIM);
    transpose_cvt_kernel<<<dim3(HDIM/32,  IDIM/32, NEXP), tb>>>(w_down_e, p_wdnT, IDIM, HDIM);

    // 1. rmsnorm1 -> fp16
    rmsnorm_kernel<<<TTOK, 256>>>(hidden, w_ln1, p_h16, nullptr);
    // 2. qkv = h @ w_qkv
    hgemm<<<dim3(QKVW/128, TTOK/128), 128, HG_SMEM>>>(TTOK, QKVW, HDIM, p_h16, p_wqkvT, 0, p_qkv, nullptr, 0);
    // 3. rope + l2 norm -> fp16 q/k
    rope_l2_kernel<<<dim3(TTOK, 5), 128>>>(p_qkv, freqs, p_q16, p_k16);
    // 4. flash attention -> fp16 O
    flash_attn_kernel<<<dim3(BATCH*NH, SEQ/64), 128, FA_SMEM>>>(p_q16, p_k16, p_qkv, p_o16);
    // 5. x2 = hidden + o @ w_o
    hgemm<<<dim3(HDIM/128, TTOK/128), 128, HG_SMEM>>>(TTOK, HDIM, NH*HD, p_o16, p_woT, 0, p_x2, hidden, 0);
    // 6. rmsnorm2 -> fp16 + fp32
    rmsnorm_kernel<<<TTOK, 256>>>(p_x2, w_ln2, p_h2_16, p_h2);
    // 7. router (fp32 logits)
    zero_cnt_kernel<<<1, 32>>>();
    router_kernel<<<TTOK, 256>>>(p_h2, w_router);
    offsets_kernel<<<1, 32>>>();
    slot_kernel<<<TTOK/256, 256>>>();
    // 8. shared expert
    hgemm<<<dim3(2*IDIM/128, TTOK/128), 128, HG_SMEM>>>(TTOK, 2*IDIM, HDIM, p_h2_16, p_wshguT, 0, p_gus, nullptr, 0);
    silu_mul_kernel<<<(TTOK*IDIM + 255)/256, 256>>>(p_gus, p_acs16);
    hgemm<<<dim3(HDIM/128, TTOK/128), 128, HG_SMEM>>>(TTOK, HDIM, IDIM, p_acs16, p_wshdnT, 0, out, p_x2, 0);
    // 9. routed experts (top-1, gathered)
    hgemm<<<dim3(2*IDIM/128, TTOK/128, NEXP), 128, HG_SMEM>>>(TTOK, 2*IDIM, HDIM, p_h2_16, p_wguT,
                                                              (size_t)2*IDIM*HDIM, p_gur, nullptr, 1);
    silu_mul_kernel<<<(TTOK*IDIM + 255)/256, 256>>>(p_gur, p_acr16);
    hgemm<<<dim3(HDIM/128, TTOK/128, NEXP), 128, HG_SMEM>>>(TTOK, HDIM, IDIM, p_acr16, p_wdnT,
                                                            (size_t)IDIM*HDIM, out, nullptr, 2);
}

// round 10
// speedup vs baseline: 1.0579x; 1.0579x over previous
#include <cuda_runtime.h>
#include <cuda_fp16.h>
#include <stdint.h>
#include <math.h>

// ---------------- problem constants ----------------
#define BATCH 2
#define SEQ   1024
#define HDIM  2048
#define NH    16
#define NKV   4
#define HD    128
#define NEXP  8
#define IDIM  2048
#define TTOK  (BATCH*SEQ)          // 2048 tokens
#define QKVW  ((NH+2*NKV)*HD)      // 3072
#define SCALE 0.08838834764831845f // 128^-0.5
#define EPS_RMS 1e-5f
#define EPS_L2  1e-6f

// ---------------- scratch (device globals; no allocation allowed) ----------
__device__ float  g_qkv [TTOK*QKVW];
__device__ float  g_x2  [TTOK*HDIM];
__device__ float  g_h2  [TTOK*HDIM];
__device__ float  g_gus [TTOK*2*IDIM];
__device__ float  g_gur [TTOK*2*IDIM];

__device__ __half g_h16  [TTOK*HDIM];
__device__ __half g_q16  [TTOK*NH*HD];
__device__ __half g_k16  [TTOK*NKV*HD];
__device__ __half g_o16  [TTOK*NH*HD];
__device__ __half g_h2_16[TTOK*HDIM];
__device__ __half g_acs16[TTOK*IDIM];
__device__ __half g_acr16[TTOK*IDIM];

__device__ int   g_cnt[NEXP];
__device__ int   g_off[NEXP];
__device__ int   g_tok_expert[TTOK];
__device__ int   g_tok_rank[TTOK];
__device__ float g_tok_scale[TTOK];
__device__ int   g_slot_tok[TTOK];

// ---------------- common PTX helpers ----------------
__device__ __forceinline__ void cp16(uint32_t dst, const void* src) {
    asm volatile("cp.async.ca.shared.global [%0], [%1], 16;" :: "r"(dst), "l"(src));
}
__device__ __forceinline__ uint32_t f2tf32(float f) {
    uint32_t u;
    asm("cvt.rna.tf32.f32 %0, %1;" : "=r"(u) : "f"(f));
    return u;
}
__device__ __forceinline__ void mma_tf32(float* c, const uint32_t* a, const uint32_t* b) {
    asm volatile(
        "mma.sync.aligned.m16n8k8.row.col.f32.tf32.tf32.f32 "
        "{%0,%1,%2,%3}, {%4,%5,%6,%7}, {%8,%9}, {%0,%1,%2,%3};"
        : "+f"(c[0]), "+f"(c[1]), "+f"(c[2]), "+f"(c[3])
        : "r"(a[0]), "r"(a[1]), "r"(a[2]), "r"(a[3]), "r"(b[0]), "r"(b[1]));
}
__device__ __forceinline__ void mma_f16(float* c, const uint32_t* a, const uint32_t* b) {
    asm volatile(
        "mma.sync.aligned.m16n8k16.row.col.f32.f16.f16.f32 "
        "{%0,%1,%2,%3}, {%4,%5,%6,%7}, {%8,%9}, {%0,%1,%2,%3};"
        : "+f"(c[0]), "+f"(c[1]), "+f"(c[2]), "+f"(c[3])
        : "r"(a[0]), "r"(a[1]), "r"(a[2]), "r"(a[3]), "r"(b[0]), "r"(b[1]));
}
__device__ __forceinline__ void ldsm_x4(uint32_t& r0, uint32_t& r1, uint32_t& r2, uint32_t& r3,
                                        uint32_t addr) {
    asm volatile("ldmatrix.sync.aligned.m8n8.x4.shared.b16 {%0,%1,%2,%3}, [%4];"
                 : "=r"(r0), "=r"(r1), "=r"(r2), "=r"(r3) : "r"(addr));
}
__device__ __forceinline__ void ldsm_x4_t(uint32_t& r0, uint32_t& r1, uint32_t& r2, uint32_t& r3,
                                          uint32_t addr) {
    asm volatile("ldmatrix.sync.aligned.m8n8.x4.trans.shared.b16 {%0,%1,%2,%3}, [%4];"
                 : "=r"(r0), "=r"(r1), "=r"(r2), "=r"(r3) : "r"(addr));
}

// ---------------- RMSNorm (fp16 out, optional fp32 out) ----------------
__global__ void rmsnorm_kernel(const float* __restrict__ x,
                               const float* __restrict__ w,
                               __half* __restrict__ out16,
                               float* __restrict__ out32)
{
    int t = blockIdx.x;
    const float* xr = x + (size_t)t * HDIM;
    float ss = 0.f;
    for (int i = threadIdx.x; i < HDIM; i += blockDim.x) {
        float v = xr[i];
        ss += v * v;
    }
    __shared__ float red[8];
    int lane = threadIdx.x & 31, wid = threadIdx.x >> 5;
    #pragma unroll
    for (int o = 16; o; o >>= 1) ss += __shfl_xor_sync(0xffffffffu, ss, o);
    if (lane == 0) red[wid] = ss;
    __syncthreads();
    if (wid == 0) {
        float v = (lane < (blockDim.x >> 5)) ? red[lane] : 0.f;
        #pragma unroll
        for (int o = 16; o; o >>= 1) v += __shfl_xor_sync(0xffffffffu, v, o);
        if (lane == 0) red[0] = v;
    }
    __syncthreads();
    float r = rsqrtf(red[0] / (float)HDIM + EPS_RMS);
    for (int i = threadIdx.x; i < HDIM; i += blockDim.x) {
        float v = xr[i] * r * w[i];
        out16[(size_t)t * HDIM + i] = __float2half(v);
        if (out32) out32[(size_t)t * HDIM + i] = v;
    }
}

// =====================================================================
// fp16 tensor-core GEMM, NO weight pre-transpose:
//   C[M,N] = A[M,K] @ B[K,N]  (+D)
// A fp16 [M][K] (cp.async, padded smem, ldmatrix.x4)
// B fp32 [K][N] (cp.async fp32 stage -> in-smem cvt to fp16 [k][n] -> ldmatrix.x4.trans)
// CTA 128x128, K-tile 32, 128 threads, warp tile 64x64, mma m16n8k16.
// modes: 0 plain(+D), 1 expert gate_up (gather+scale), 2 expert down (scatter)
// =====================================================================
#define AHS 40     // A smem stride (halves)
#define BFS 132    // B fp32 stage stride (floats)
#define BHS 136    // B fp16 stride (halves)
#define A_BUF   (128*AHS*2)     // 10240
#define BF_BUF  (32*BFS*4)      // 16896
#define BH_BUF  (32*BHS*2)      // 8704
#define A_OFF   0
#define BF_OFF  (2*A_BUF)               // 20480
#define BH_OFF  (BF_OFF + 2*BF_BUF)     // 54272
#define HG_SMEM (BH_OFF + BH_BUF)       // 62976

__global__ __launch_bounds__(128)
void hgemm(int M, int N, int K,
           const __half* __restrict__ A,
           const float* __restrict__ B, size_t b_expert_stride,
           float* __restrict__ C,
           const float* __restrict__ D,
           int mode)
{
    extern __shared__ char sm[];
    uint32_t smBase = (uint32_t)__cvta_generic_to_shared(sm);

    int crow = blockIdx.y * 128;
    int ccol = blockIdx.x * 128;
    int cnt = M, off = 0;
    if (mode) {
        int e = blockIdx.z;
        cnt = g_cnt[e];
        off = g_off[e];
        B += (size_t)e * b_expert_stride;
        if (crow >= cnt) return;
    }

    const int tid = threadIdx.x;
    const int warp = tid >> 5, lane = tid & 31;
    const int g = lane >> 2, tig = lane & 3;
    const int wm = (warp >> 1) * 64;
    const int wn = (warp & 1) * 64;

    // ---- A staging: 512 16B chunks -> 4/thread ----
    const __half* a_src[4];
    uint32_t a_off_s[4];
    #pragma unroll
    for (int i = 0; i < 4; i++) {
        int idx = tid + i * 128;
        int r = idx >> 2, c8 = (idx & 3) * 8;
        int gr = crow + r;
        int arow;
        if (mode == 1)      arow = g_slot_tok[off + (gr < cnt ? gr : cnt - 1)];
        else if (mode == 2) arow = off + (gr < cnt ? gr : cnt - 1);
        else                arow = gr;
        a_src[i] = A + (size_t)arow * K + c8;
        a_off_s[i] = (uint32_t)((r * AHS + c8) * 2);
    }
    // ---- B fp32 staging: 1024 16B chunks -> 8/thread ----
    const float* b_src[8];
    uint32_t b_off_s[8];
    #pragma unroll
    for (int i = 0; i < 8; i++) {
        int idx = tid + i * 128;
        int r = idx >> 5, c4 = (idx & 31) * 4;
        b_src[i] = B + (size_t)r * N + ccol + c4;
        b_off_s[i] = (uint32_t)((r * BFS + c4) * 4);
    }

    // ldmatrix per-lane offsets
    int lr8 = lane & 7, seg1 = (lane >> 3) & 1, seg2 = lane >> 4;
    uint32_t a_frag = (uint32_t)(((wm + lr8 + seg1 * 8) * AHS + seg2 * 8) * 2);
    // B trans frag: lane -> k row (lane&15), n half (lane>>4)*8
    int bk = lane & 15, bn = (lane >> 4) * 8;

    float acc[4][8][4];
    #pragma unroll
    for (int mt = 0; mt < 4; mt++)
        #pragma unroll
        for (int nt = 0; nt < 8; nt++)
            #pragma unroll
            for (int r = 0; r < 4; r++) acc[mt][nt][r] = 0.f;

    const int KT = K / 32;

    // prefetch tile 0
    #pragma unroll
    for (int i = 0; i < 4; i++) cp16(smBase + A_OFF + a_off_s[i], a_src[i]);
    #pragma unroll
    for (int i = 0; i < 8; i++) cp16(smBase + BF_OFF + b_off_s[i], b_src[i]);
    asm volatile("cp.async.commit_group;");

    for (int kt = 0; kt < KT; kt++) {
        int buf = kt & 1;
        asm volatile("cp.async.wait_group 0;");
        __syncthreads();

        // prefetch next tile
        if (kt + 1 < KT) {
            int k0 = (kt + 1) * 32;
            int nbuf = buf ^ 1;
            #pragma unroll
            for (int i = 0; i < 4; i++)
                cp16(smBase + A_OFF + nbuf * A_BUF + a_off_s[i], a_src[i] + k0);
            #pragma unroll
            for (int i = 0; i < 8; i++)
                cp16(smBase + BF_OFF + nbuf * BF_BUF + b_off_s[i], b_src[i] + (size_t)k0 * N);
            asm volatile("cp.async.commit_group;");
        }

        // convert staged fp32 B -> fp16 [k][n]
        {
            const float* bf = (const float*)(sm + BF_OFF + buf * BF_BUF);
            __half* bh = (__half*)(sm + BH_OFF);
            #pragma unroll
            for (int i = 0; i < 8; i++) {
                int f = tid + i * 128;
                int r = f >> 5, c4 = (f & 31) * 4;
                float4 v = *(const float4*)(bf + r * BFS + c4);
                *(__half2*)(bh + r * BHS + c4)     = __floats2half2_rn(v.x, v.y);
                *(__half2*)(bh + r * BHS + c4 + 2) = __floats2half2_rn(v.z, v.w);
            }
        }
        __syncthreads();

        uint32_t aB = smBase + A_OFF + buf * A_BUF + a_frag;
        uint32_t bhB = smBase + BH_OFF;

        uint32_t ua[2][4][4], ub[2][8][2];
        #pragma unroll
        for (int ks = 0; ks < 2; ks++) {
            uint32_t ka = aB + ks * 32;
            #pragma unroll
            for (int mt = 0; mt < 4; mt++)
                ldsm_x4(ua[ks][mt][0], ua[ks][mt][1], ua[ks][mt][2], ua[ks][mt][3],
                        ka + mt * (16 * AHS * 2));
            #pragma unroll
            for (int j = 0; j < 4; j++) {
                uint32_t addr = bhB + (uint32_t)(((ks * 16 + bk) * BHS + wn + bn + j * 16) * 2);
                ldsm_x4_t(ub[ks][2*j][0], ub[ks][2*j][1], ub[ks][2*j+1][0], ub[ks][2*j+1][1],
                          addr);
            }
        }
        #pragma unroll
        for (int ks = 0; ks < 2; ks++)
            #pragma unroll
            for (int mt = 0; mt < 4; mt++)
                #pragma unroll
                for (int nt = 0; nt < 8; nt++)
                    mma_f16(acc[mt][nt], ua[ks][mt], ub[ks][nt]);
        __syncthreads();
    }

    // ---------------- epilogue ----------------
    #pragma unroll
    for (int mt = 0; mt < 4; mt++) {
        #pragma unroll
        for (int h = 0; h < 2; h++) {
            int rl = wm + mt * 16 + g + h * 8;
            int gr = crow + rl;
            if (mode == 0) {
                size_t rbase = (size_t)gr * N;
                #pragma unroll
                for (int nt = 0; nt < 8; nt++) {
                    int c = ccol + wn + nt * 8 + tig * 2;
                    float v0 = acc[mt][nt][h * 2 + 0];
                    float v1 = acc[mt][nt][h * 2 + 1];
                    if (D) {
                        float2 dv = *(const float2*)(D + rbase + c);
                        v0 += dv.x; v1 += dv.y;
                    }
                    *(float2*)(C + rbase + c) = make_float2(v0, v1);
                }
            } else if (mode == 1) {
                if (gr < cnt) {
                    int slot = off + gr;
                    float s = g_tok_scale[g_slot_tok[slot]];
                    size_t rbase = (size_t)slot * N;
                    #pragma unroll
                    for (int nt = 0; nt < 8; nt++) {
                        int c = ccol + wn + nt * 8 + tig * 2;
                        *(float2*)(C + rbase + c) =
                            make_float2(s * acc[mt][nt][h * 2 + 0],
                                        s * acc[mt][nt][h * 2 + 1]);
                    }
                }
            } else {
                if (gr < cnt) {
                    int tok = g_slot_tok[off + gr];
                    size_t rbase = (size_t)tok * N;
                    #pragma unroll
                    for (int nt = 0; nt < 8; nt++) {
                        int c = ccol + wn + nt * 8 + tig * 2;
                        float2* cp = (float2*)(C + rbase + c);
                        float2 cv = *cp;
                        cv.x += acc[mt][nt][h * 2 + 0];
                        cv.y += acc[mt][nt][h * 2 + 1];
                        *cp = cv;
                    }
                }
            }
        }
    }
}

// ---------------- RoPE + L2-norm for q & k -> fp16 ----------------
__global__ void rope_l2_kernel(const float* __restrict__ qkv,
                               const float* __restrict__ freqs,
                               __half* __restrict__ qout,
                               __half* __restrict__ kout)
{
    int t = blockIdx.x;
    int lane = threadIdx.x & 31, w = threadIdx.x >> 5;
    int hh = blockIdx.y * 4 + w;
    int s = t & (SEQ - 1);

    const float* src;
    __half* dst;
    if (hh < NH) {
        src = qkv + (size_t)t * QKVW + hh * HD;
        dst = qout + (size_t)t * NH * HD + hh * HD;
    } else {
        int kv = hh - NH;
        src = qkv + (size_t)t * QKVW + NH * HD + kv * HD;
        dst = kout + (size_t)t * NKV * HD + kv * HD;
    }
    float4 xv = *(const float4*)(src + lane * 4);
    float4 fv = *(const float4*)(freqs + (size_t)s * HD + lane * 4);
    float o0 = xv.x * fv.x - xv.y * fv.y;
    float o1 = xv.x * fv.y + xv.y * fv.x;
    float o2 = xv.z * fv.z - xv.w * fv.w;
    float o3 = xv.z * fv.w + xv.w * fv.z;
    float ss = o0*o0 + o1*o1 + o2*o2 + o3*o3;
    #pragma unroll
    for (int o = 16; o; o >>= 1) ss += __shfl_xor_sync(0xffffffffu, ss, o);
    float r = rsqrtf(ss / (float)HD + EPS_L2);
    __half2 p0 = __floats2half2_rn(o0 * r, o1 * r);
    __half2 p1 = __floats2half2_rn(o2 * r, o3 * r);
    *(__half2*)(dst + lane * 4)     = p0;
    *(__half2*)(dst + lane * 4 + 2) = p1;
}

// =====================================================================
// flash attention: fp16 S-path (Q,K fp16 mma), tf32 P@V. 64 q rows/block.
// =====================================================================
#define KH_STRIDE 136   // halves
#define VS_STRIDE 136   // floats
#define P_STRIDE  68    // floats
#define FA_SMEM   (64*KH_STRIDE*2 + 64*VS_STRIDE*4 + 64*P_STRIDE*4)

__global__ __launch_bounds__(128)
void flash_attn_kernel(const __half* __restrict__ q,
                       const __half* __restrict__ k,
                       const float* __restrict__ qkv,
                       __half* __restrict__ o)
{
    extern __shared__ char fsm[];
    __half* Ks = (__half*)fsm;                         // [64][KH_STRIDE]
    float*  Vs = (float*)(fsm + 64 * KH_STRIDE * 2);   // [64][VS_STRIDE]
    float*  Ps = Vs + 64 * VS_STRIDE;                  // [64][P_STRIDE]

    int bh = blockIdx.x;
    int b = bh >> 4, h = bh & 15;
    int kvh = h >> 2;
    int q0 = blockIdx.y * 64;

    int tid = threadIdx.x, warp = tid >> 5, lane = tid & 31;
    int g = lane >> 2, tig = lane & 3;

    int qr0 = q0 + warp * 16 + g;
    int qr1 = qr0 + 8;
    const __half* qb0 = q + ((size_t)(b * SEQ + qr0) * NH + h) * HD;
    const __half* qb1 = q + ((size_t)(b * SEQ + qr1) * NH + h) * HD;
    uint32_t qa[8][4];
    #pragma unroll
    for (int ks = 0; ks < 8; ks++) {
        int c = ks * 16 + tig * 2;
        qa[ks][0] = *(const uint32_t*)&qb0[c];
        qa[ks][1] = *(const uint32_t*)&qb1[c];
        qa[ks][2] = *(const uint32_t*)&qb0[c + 8];
        qa[ks][3] = *(const uint32_t*)&qb1[c + 8];
    }

    float oacc[16][4];
    #pragma unroll
    for (int dt = 0; dt < 16; dt++)
        #pragma unroll
        for (int r = 0; r < 4; r++) oacc[dt][r] = 0.f;
    float m0 = -1e30f, m1 = -1e30f, l0 = 0.f, l1 = 0.f;

    uint32_t ksb = (uint32_t)__cvta_generic_to_shared(Ks);
    uint32_t vsb = (uint32_t)__cvta_generic_to_shared(Vs);

    const int ktiles = blockIdx.y + 1;
    for (int kt = 0; kt < ktiles; kt++) {
        const __half* kptr = k + ((size_t)(b * SEQ + kt * 64) * NKV + kvh) * HD;
        const float*  vptr = qkv + (size_t)(b * SEQ + kt * 64) * QKVW + (NH + NKV) * HD + kvh * HD;
        #pragma unroll
        for (int it = 0; it < 8; it++) {
            int idx = tid + it * 128;
            int r = idx >> 4, c = (idx & 15) * 8;
            cp16(ksb + (uint32_t)(r * KH_STRIDE + c) * 2, kptr + (size_t)r * (NKV * HD) + c);
        }
        #pragma unroll
        for (int it = 0; it < 16; it++) {
            int idx = tid + it * 128;
            int r = idx >> 5, c = (idx & 31) * 4;
            cp16(vsb + (uint32_t)(r * VS_STRIDE + c) * 4, vptr + (size_t)r * QKVW + c);
        }
        asm volatile("cp.async.commit_group;");
        asm volatile("cp.async.wait_group 0;");
        __syncthreads();

        float sacc[8][4];
        #pragma unroll
        for (int nt = 0; nt < 8; nt++)
            #pragma unroll
            for (int r = 0; r < 4; r++) sacc[nt][r] = 0.f;

        #pragma unroll
        for (int ks = 0; ks < 8; ks++) {
            int kb = ks * 16 + tig * 2;
            uint32_t ub[8][2];
            #pragma unroll
            for (int nt = 0; nt < 8; nt++) {
                int kr = nt * 8 + g;
                ub[nt][0] = *(const uint32_t*)&Ks[kr * KH_STRIDE + kb];
                ub[nt][1] = *(const uint32_t*)&Ks[kr * KH_STRIDE + kb + 8];
            }
            #pragma unroll
            for (int nt = 0; nt < 8; nt++)
                mma_f16(sacc[nt], qa[ks], ub[nt]);
        }

        bool diag = (kt == ktiles - 1);
        float rmax0 = -1e30f, rmax1 = -1e30f;
        #pragma unroll
        for (int nt = 0; nt < 8; nt++) {
            int c0 = kt * 64 + nt * 8 + tig * 2;
            float s0 = sacc[nt][0] * SCALE;
            float s1 = sacc[nt][1] * SCALE;
            float s2 = sacc[nt][2] * SCALE;
            float s3 = sacc[nt][3] * SCALE;
            if (diag) {
                if (c0 > qr0)     s0 = -1e30f;
                if (c0 + 1 > qr0) s1 = -1e30f;
                if (c0 > qr1)     s2 = -1e30f;
                if (c0 + 1 > qr1) s3 = -1e30f;
            }
            sacc[nt][0] = s0; sacc[nt][1] = s1;
            sacc[nt][2] = s2; sacc[nt][3] = s3;
            rmax0 = fmaxf(rmax0, fmaxf(s0, s1));
            rmax1 = fmaxf(rmax1, fmaxf(s2, s3));
        }
        #pragma unroll
        for (int off = 1; off <= 2; off <<= 1) {
            rmax0 = fmaxf(rmax0, __shfl_xor_sync(0xffffffffu, rmax0, off));
            rmax1 = fmaxf(rmax1, __shfl_xor_sync(0xffffffffu, rmax1, off));
        }
        float mn0 = fmaxf(m0, rmax0);
        float mn1 = fmaxf(m1, rmax1);
        float corr0 = __expf(m0 - mn0);
        float corr1 = __expf(m1 - mn1);
        m0 = mn0; m1 = mn1;

        float psum0 = 0.f, psum1 = 0.f;
        #pragma unroll
        for (int nt = 0; nt < 8; nt++) {
            float p0 = __expf(sacc[nt][0] - mn0);
            float p1 = __expf(sacc[nt][1] - mn0);
            float p2 = __expf(sacc[nt][2] - mn1);
            float p3 = __expf(sacc[nt][3] - mn1);
            psum0 += p0 + p1;
            psum1 += p2 + p3;
            int c = nt * 8 + tig * 2;
            *(float2*)&Ps[(warp * 16 + g) * P_STRIDE + c]     = make_float2(p0, p1);
            *(float2*)&Ps[(warp * 16 + g + 8) * P_STRIDE + c] = make_float2(p2, p3);
        }
        #pragma unroll
        for (int off = 1; off <= 2; off <<= 1) {
            psum0 += __shfl_xor_sync(0xffffffffu, psum0, off);
            psum1 += __shfl_xor_sync(0xffffffffu, psum1, off);
        }
        l0 = l0 * corr0 + psum0;
        l1 = l1 * corr1 + psum1;

        #pragma unroll
        for (int dt = 0; dt < 16; dt++) {
            oacc[dt][0] *= corr0; oacc[dt][1] *= corr0;
            oacc[dt][2] *= corr1; oacc[dt][3] *= corr1;
        }
        __syncwarp();

        #pragma unroll
        for (int ks = 0; ks < 8; ks++) {
            int k8 = ks * 8;
            uint32_t pa[4];
            pa[0] = f2tf32(Ps[(warp * 16 + g) * P_STRIDE + k8 + tig]);
            pa[1] = f2tf32(Ps[(warp * 16 + g + 8) * P_STRIDE + k8 + tig]);
            pa[2] = f2tf32(Ps[(warp * 16 + g) * P_STRIDE + k8 + tig + 4]);
            pa[3] = f2tf32(Ps[(warp * 16 + g + 8) * P_STRIDE + k8 + tig + 4]);
            #pragma unroll
            for (int dt = 0; dt < 16; dt++) {
                uint32_t vb[2];
                vb[0] = f2tf32(Vs[(k8 + tig) * VS_STRIDE + dt * 8 + g]);
                vb[1] = f2tf32(Vs[(k8 + tig + 4) * VS_STRIDE + dt * 8 + g]);
                mma_tf32(oacc[dt], pa, vb);
            }
        }
        __syncthreads();
    }

    float inv0 = 1.f / l0, inv1 = 1.f / l1;
    __half* ob0 = o + ((size_t)(b * SEQ + qr0) * NH + h) * HD;
    __half* ob1 = o + ((size_t)(b * SEQ + qr1) * NH + h) * HD;
    #pragma unroll
    for (int dt = 0; dt < 16; dt++) {
        int d = dt * 8 + tig * 2;
        *(__half2*)(ob0 + d) = __floats2half2_rn(oacc[dt][0] * inv0, oacc[dt][1] * inv0);
        *(__half2*)(ob1 + d) = __floats2half2_rn(oacc[dt][2] * inv1, oacc[dt][3] * inv1);
    }
}

// ---------------- router ----------------
__global__ void zero_cnt_kernel()
{
    if (threadIdx.x < NEXP) g_cnt[threadIdx.x] = 0;
}

__global__ void router_kernel(const float* __restrict__ h2,
                              const float* __restrict__ wr)
{
    int t = blockIdx.x;
    const float* hrow = h2 + (size_t)t * HDIM;
    float l[NEXP];
    #pragma unroll
    for (int e = 0; e < NEXP; e++) l[e] = 0.f;
    for (int kk = threadIdx.x; kk < HDIM; kk += blockDim.x) {
        float hv = hrow[kk];
        const float* wrow = wr + (size_t)kk * NEXP;
        #pragma unroll
        for (int e = 0; e < NEXP; e++) l[e] += hv * wrow[e];
    }
    __shared__ float sums[NEXP];
    if (threadIdx.x < NEXP) sums[threadIdx.x] = 0.f;
    __syncthreads();
    #pragma unroll
    for (int e = 0; e < NEXP; e++) {
        float v = l[e];
        #pragma unroll
        for (int o = 16; o; o >>= 1) v += __shfl_xor_sync(0xffffffffu, v, o);
        if ((threadIdx.x & 31) == 0) atomicAdd(&sums[e], v);
    }
    __syncthreads();
    if (threadIdx.x == 0) {
        int best = 0;
        float bv = sums[0];
        #pragma unroll
        for (int e = 1; e < NEXP; e++)
            if (sums[e] > bv) { bv = sums[e]; best = e; }
        g_tok_expert[t] = best;
        g_tok_scale[t]  = 1.f / (1.f + __expf(-bv));
        g_tok_rank[t]   = atomicAdd(&g_cnt[best], 1);
    }
}

__global__ void offsets_kernel()
{
    if (threadIdx.x == 0) {
        int run = 0;
        for (int e = 0; e < NEXP; e++) { g_off[e] = run; run += g_cnt[e]; }
    }
}

__global__ void slot_kernel()
{
    int t = blockIdx.x * blockDim.x + threadIdx.x;
    if (t < TTOK)
        g_slot_tok[g_off[g_tok_expert[t]] + g_tok_rank[t]] = t;
}

// ---------------- SiLU(g)*u -> fp16 ----------------
__global__ void silu_mul_kernel(const float* __restrict__ gu,
                                __half* __restrict__ out)
{
    int i = blockIdx.x * blockDim.x + threadIdx.x;
    if (i >= TTOK * IDIM) return;
    int row = i / IDIM, col = i - row * IDIM;
    float g = gu[(size_t)row * 2 * IDIM + col];
    float u = gu[(size_t)row * 2 * IDIM + IDIM + col];
    float sg = 1.f / (1.f + __expf(-g));
    out[i] = __float2half(u * g * sg);
}

// ---------------- launch ----------------
extern "C" void kernel_launch(void* const* d_in, const int* in_sizes, int n_in,
                              void* d_out, int out_size)
{
    const float* hidden   = (const float*)d_in[0];
    const float* freqs    = (const float*)d_in[1];
    const float* w_ln1    = (const float*)d_in[2];
    const float* w_qkv    = (const float*)d_in[3];
    const float* w_o      = (const float*)d_in[4];
    const float* w_ln2    = (const float*)d_in[5];
    const float* w_router = (const float*)d_in[6];
    const float* w_gu_e   = (const float*)d_in[7];
    const float* w_down_e = (const float*)d_in[8];
    const float* w_sh_gu  = (const float*)d_in[9];
    const float* w_sh_dn  = (const float*)d_in[10];
    float* out = (float*)d_out;

    float *p_qkv, *p_x2, *p_h2, *p_gus, *p_gur;
    __half *p_h16, *p_q16, *p_k16, *p_o16, *p_h2_16, *p_acs16, *p_acr16;
    cudaGetSymbolAddress((void**)&p_qkv,   g_qkv);
    cudaGetSymbolAddress((void**)&p_x2,    g_x2);
    cudaGetSymbolAddress((void**)&p_h2,    g_h2);
    cudaGetSymbolAddress((void**)&p_gus,   g_gus);
    cudaGetSymbolAddress((void**)&p_gur,   g_gur);
    cudaGetSymbolAddress((void**)&p_h16,   g_h16);
    cudaGetSymbolAddress((void**)&p_q16,   g_q16);
    cudaGetSymbolAddress((void**)&p_k16,   g_k16);
    cudaGetSymbolAddress((void**)&p_o16,   g_o16);
    cudaGetSymbolAddress((void**)&p_h2_16, g_h2_16);
    cudaGetSymbolAddress((void**)&p_acs16, g_acs16);
    cudaGetSymbolAddress((void**)&p_acr16, g_acr16);

    static int attr_set = 0;
    if (!attr_set) {
        cudaFuncSetAttribute(flash_attn_kernel,
                             cudaFuncAttributeMaxDynamicSharedMemorySize, FA_SMEM);
        cudaFuncSetAttribute(hgemm,
                             cudaFuncAttributeMaxDynamicSharedMemorySize, HG_SMEM);
        attr_set = 1;
    }

    // 1. rmsnorm1 -> fp16
    rmsnorm_kernel<<<TTOK, 256>>>(hidden, w_ln1, p_h16, nullptr);
    // 2. qkv = h @ w_qkv
    hgemm<<<dim3(QKVW/128, TTOK/128), 128, HG_SMEM>>>(TTOK, QKVW, HDIM, p_h16, w_qkv, 0, p_qkv, nullptr, 0);
    // 3. rope + l2 norm -> fp16 q/k
    rope_l2_kernel<<<dim3(TTOK, 5), 128>>>(p_qkv, freqs, p_q16, p_k16);
    // 4. flash attention -> fp16 O
    flash_attn_kernel<<<dim3(BATCH*NH, SEQ/64), 128, FA_SMEM>>>(p_q16, p_k16, p_qkv, p_o16);
    // 5. x2 = hidden + o @ w_o
    hgemm<<<dim3(HDIM/128, TTOK/128), 128, HG_SMEM>>>(TTOK, HDIM, NH*HD, p_o16, w_o, 0, p_x2, hidden, 0);
    // 6. rmsnorm2 -> fp16 + fp32
    rmsnorm_kernel<<<TTOK, 256>>>(p_x2, w_ln2, p_h2_16, p_h2);
    // 7. router (fp32 logits)
    zero_cnt_kernel<<<1, 32>>>();
    router_kernel<<<TTOK, 256>>>(p_h2, w_router);
    offsets_kernel<<<1, 32>>>();
    slot_kernel<<<TTOK/256, 256>>>();
    // 8. shared expert
    hgemm<<<dim3(2*IDIM/128, TTOK/128), 128, HG_SMEM>>>(TTOK, 2*IDIM, HDIM, p_h2_16, w_sh_gu, 0, p_gus, nullptr, 0);
    silu_mul_kernel<<<(TTOK*IDIM + 255)/256, 256>>>(p_gus, p_acs16);
    hgemm<<<dim3(HDIM/128, TTOK/128), 128, HG_SMEM>>>(TTOK, HDIM, IDIM, p_acs16, w_sh_dn, 0, out, p_x2, 0);
    // 9. routed experts (top-1, gathered)
    hgemm<<<dim3(2*IDIM/128, TTOK/128, NEXP), 128, HG_SMEM>>>(TTOK, 2*IDIM, HDIM, p_h2_16, w_gu_e,
                                                              (size_t)HDIM*2*IDIM, p_gur, nullptr, 1);
    silu_mul_kernel<<<(TTOK*IDIM + 255)/256, 256>>>(p_gur, p_acr16);
    hgemm<<<dim3(HDIM/128, TTOK/128, NEXP), 128, HG_SMEM>>>(TTOK, HDIM, IDIM, p_acr16, w_down_e,
                                                            (size_t)IDIM*HDIM, out, nullptr, 2);
}

// round 11
// speedup vs baseline: 1.2410x; 1.1730x over previous
#include <cuda_runtime.h>
#include <cuda_fp16.h>
#include <stdint.h>
#include <math.h>

// ---------------- problem constants ----------------
#define BATCH 2
#define SEQ   1024
#define HDIM  2048
#define NH    16
#define NKV   4
#define HD    128
#define NEXP  8
#define IDIM  2048
#define TTOK  (BATCH*SEQ)          // 2048 tokens
#define QKVW  ((NH+2*NKV)*HD)      // 3072
#define SCALE 0.08838834764831845f // 128^-0.5
#define EPS_RMS 1e-5f
#define EPS_L2  1e-6f

// ---------------- scratch (device globals; no allocation allowed) ----------
__device__ float  g_qkv [TTOK*QKVW];
__device__ float  g_x2  [TTOK*HDIM];
__device__ float  g_h2  [TTOK*HDIM];
__device__ float  g_gus [TTOK*2*IDIM];
__device__ float  g_gur [TTOK*2*IDIM];

__device__ __half g_h16  [TTOK*HDIM];
__device__ __half g_q16  [TTOK*NH*HD];
__device__ __half g_k16  [TTOK*NKV*HD];
__device__ __half g_o16  [TTOK*NH*HD];
__device__ __half g_h2_16[TTOK*HDIM];
__device__ __half g_acs16[TTOK*IDIM];
__device__ __half g_acr16[TTOK*IDIM];

// fp16 weights, SAME [K][N] layout as fp32 originals (no transpose)
__device__ __half g_wqkv16 [HDIM*QKVW];
__device__ __half g_wo16   [NH*HD*HDIM];
__device__ __half g_wshgu16[HDIM*2*IDIM];
__device__ __half g_wshdn16[IDIM*HDIM];
__device__ __half g_wgu16  [(size_t)NEXP*HDIM*2*IDIM];
__device__ __half g_wdn16  [(size_t)NEXP*IDIM*HDIM];

__device__ int   g_cnt[NEXP];
__device__ int   g_off[NEXP];
__device__ int   g_tok_expert[TTOK];
__device__ int   g_tok_rank[TTOK];
__device__ float g_tok_scale[TTOK];
__device__ int   g_slot_tok[TTOK];

// ---------------- common PTX helpers ----------------
__device__ __forceinline__ void cp16(uint32_t dst, const void* src) {
    asm volatile("cp.async.ca.shared.global [%0], [%1], 16;" :: "r"(dst), "l"(src));
}
__device__ __forceinline__ uint32_t f2tf32(float f) {
    uint32_t u;
    asm("cvt.rna.tf32.f32 %0, %1;" : "=r"(u) : "f"(f));
    return u;
}
__device__ __forceinline__ void mma_tf32(float* c, const uint32_t* a, const uint32_t* b) {
    asm volatile(
        "mma.sync.aligned.m16n8k8.row.col.f32.tf32.tf32.f32 "
        "{%0,%1,%2,%3}, {%4,%5,%6,%7}, {%8,%9}, {%0,%1,%2,%3};"
        : "+f"(c[0]), "+f"(c[1]), "+f"(c[2]), "+f"(c[3])
        : "r"(a[0]), "r"(a[1]), "r"(a[2]), "r"(a[3]), "r"(b[0]), "r"(b[1]));
}
__device__ __forceinline__ void mma_f16(float* c, const uint32_t* a, const uint32_t* b) {
    asm volatile(
        "mma.sync.aligned.m16n8k16.row.col.f32.f16.f16.f32 "
        "{%0,%1,%2,%3}, {%4,%5,%6,%7}, {%8,%9}, {%0,%1,%2,%3};"
        : "+f"(c[0]), "+f"(c[1]), "+f"(c[2]), "+f"(c[3])
        : "r"(a[0]), "r"(a[1]), "r"(a[2]), "r"(a[3]), "r"(b[0]), "r"(b[1]));
}
__device__ __forceinline__ void ldsm_x4(uint32_t& r0, uint32_t& r1, uint32_t& r2, uint32_t& r3,
                                        uint32_t addr) {
    asm volatile("ldmatrix.sync.aligned.m8n8.x4.shared.b16 {%0,%1,%2,%3}, [%4];"
                 : "=r"(r0), "=r"(r1), "=r"(r2), "=r"(r3) : "r"(addr));
}
__device__ __forceinline__ void ldsm_x4_t(uint32_t& r0, uint32_t& r1, uint32_t& r2, uint32_t& r3,
                                          uint32_t addr) {
    asm volatile("ldmatrix.sync.aligned.m8n8.x4.trans.shared.b16 {%0,%1,%2,%3}, [%4];"
                 : "=r"(r0), "=r"(r1), "=r"(r2), "=r"(r3) : "r"(addr));
}

// ---------------- layout-preserving fp32 -> fp16 convert ----------------
__global__ __launch_bounds__(256)
void cvt_kernel(const float* __restrict__ in, __half* __restrict__ out, size_t n)
{
    size_t i = ((size_t)blockIdx.x * 256 + threadIdx.x) * 8;
    if (i >= n) return;
    float4 v0 = *(const float4*)(in + i);
    float4 v1 = *(const float4*)(in + i + 4);
    __half2 h0 = __floats2half2_rn(v0.x, v0.y);
    __half2 h1 = __floats2half2_rn(v0.z, v0.w);
    __half2 h2 = __floats2half2_rn(v1.x, v1.y);
    __half2 h3 = __floats2half2_rn(v1.z, v1.w);
    uint4 pack;
    pack.x = *(uint32_t*)&h0; pack.y = *(uint32_t*)&h1;
    pack.z = *(uint32_t*)&h2; pack.w = *(uint32_t*)&h3;
    *(uint4*)(out + i) = pack;
}

// ---------------- RMSNorm (fp16 out, optional fp32 out) ----------------
__global__ void rmsnorm_kernel(const float* __restrict__ x,
                               const float* __restrict__ w,
                               __half* __restrict__ out16,
                               float* __restrict__ out32)
{
    int t = blockIdx.x;
    const float* xr = x + (size_t)t * HDIM;
    float ss = 0.f;
    for (int i = threadIdx.x; i < HDIM; i += blockDim.x) {
        float v = xr[i];
        ss += v * v;
    }
    __shared__ float red[8];
    int lane = threadIdx.x & 31, wid = threadIdx.x >> 5;
    #pragma unroll
    for (int o = 16; o; o >>= 1) ss += __shfl_xor_sync(0xffffffffu, ss, o);
    if (lane == 0) red[wid] = ss;
    __syncthreads();
    if (wid == 0) {
        float v = (lane < (blockDim.x >> 5)) ? red[lane] : 0.f;
        #pragma unroll
        for (int o = 16; o; o >>= 1) v += __shfl_xor_sync(0xffffffffu, v, o);
        if (lane == 0) red[0] = v;
    }
    __syncthreads();
    float r = rsqrtf(red[0] / (float)HDIM + EPS_RMS);
    for (int i = threadIdx.x; i < HDIM; i += blockDim.x) {
        float v = xr[i] * r * w[i];
        out16[(size_t)t * HDIM + i] = __float2half(v);
        if (out32) out32[(size_t)t * HDIM + i] = v;
    }
}

// =====================================================================
// fp16 tensor-core GEMM: C[M,N] = A[M,K] @ B[K,N]  (+D)
// A fp16 [M][K] (cp.async, ldmatrix.x4); B fp16 [K][N] (cp.async,
// ldmatrix.x4.trans). CTA 128x128, K-tile 32, double-buffered, 128 thr.
// modes: 0 plain(+D), 1 expert gate_up (gather+scale), 2 expert down (scatter)
// =====================================================================
#define AHS 40     // A smem stride (halves)
#define BHS 136    // B smem stride (halves)
#define A_BUF   (128*AHS*2)     // 10240
#define BH_BUF  (32*BHS*2)      // 8704
#define B_OFF   (2*A_BUF)       // 20480
#define HG_SMEM (B_OFF + 2*BH_BUF)  // 37888

__global__ __launch_bounds__(128)
void hgemm(int M, int N, int K,
           const __half* __restrict__ A,
           const __half* __restrict__ B, size_t b_expert_stride,
           float* __restrict__ C,
           const float* __restrict__ D,
           int mode)
{
    extern __shared__ char sm[];
    uint32_t smBase = (uint32_t)__cvta_generic_to_shared(sm);

    int crow = blockIdx.y * 128;
    int ccol = blockIdx.x * 128;
    int cnt = M, off = 0;
    if (mode) {
        int e = blockIdx.z;
        cnt = g_cnt[e];
        off = g_off[e];
        B += (size_t)e * b_expert_stride;
        if (crow >= cnt) return;
    }

    const int tid = threadIdx.x;
    const int warp = tid >> 5, lane = tid & 31;
    const int g = lane >> 2, tig = lane & 3;
    const int wm = (warp >> 1) * 64;
    const int wn = (warp & 1) * 64;

    // ---- A staging: 512 16B chunks -> 4/thread ----
    const __half* a_src[4];
    uint32_t a_off_s[4];
    #pragma unroll
    for (int i = 0; i < 4; i++) {
        int idx = tid + i * 128;
        int r = idx >> 2, c8 = (idx & 3) * 8;
        int gr = crow + r;
        int arow;
        if (mode == 1)      arow = g_slot_tok[off + (gr < cnt ? gr : cnt - 1)];
        else if (mode == 2) arow = off + (gr < cnt ? gr : cnt - 1);
        else                arow = gr;
        a_src[i] = A + (size_t)arow * K + c8;
        a_off_s[i] = (uint32_t)((r * AHS + c8) * 2);
    }
    // ---- B staging: 32 rows x 128 halves = 512 16B chunks -> 4/thread ----
    const __half* b_src[4];
    uint32_t b_off_s[4];
    #pragma unroll
    for (int i = 0; i < 4; i++) {
        int idx = tid + i * 128;
        int r = idx >> 4, c8 = (idx & 15) * 8;
        b_src[i] = B + (size_t)r * N + ccol + c8;
        b_off_s[i] = (uint32_t)((r * BHS + c8) * 2);
    }

    // ldmatrix per-lane offsets
    int lr8 = lane & 7, seg1 = (lane >> 3) & 1, seg2 = lane >> 4;
    uint32_t a_frag = (uint32_t)(((wm + lr8 + seg1 * 8) * AHS + seg2 * 8) * 2);
    int bk = lane & 15, bn = (lane >> 4) * 8;   // trans frag: k row, n half

    float acc[4][8][4];
    #pragma unroll
    for (int mt = 0; mt < 4; mt++)
        #pragma unroll
        for (int nt = 0; nt < 8; nt++)
            #pragma unroll
            for (int r = 0; r < 4; r++) acc[mt][nt][r] = 0.f;

    const int KT = K / 32;

    // prefetch stage 0
    #pragma unroll
    for (int i = 0; i < 4; i++) {
        cp16(smBase + a_off_s[i], a_src[i]);
        cp16(smBase + B_OFF + b_off_s[i], b_src[i]);
    }
    asm volatile("cp.async.commit_group;");

    for (int kt = 0; kt < KT; kt++) {
        int buf = kt & 1;
        if (kt + 1 < KT) {
            int k0 = (kt + 1) * 32;
            int nbuf = buf ^ 1;
            #pragma unroll
            for (int i = 0; i < 4; i++) {
                cp16(smBase + nbuf * A_BUF + a_off_s[i], a_src[i] + k0);
                cp16(smBase + B_OFF + nbuf * BH_BUF + b_off_s[i], b_src[i] + (size_t)k0 * N);
            }
            asm volatile("cp.async.commit_group;");
            asm volatile("cp.async.wait_group 1;");
        } else {
            asm volatile("cp.async.wait_group 0;");
        }
        __syncthreads();

        uint32_t aB  = smBase + buf * A_BUF + a_frag;
        uint32_t bhB = smBase + B_OFF + buf * BH_BUF;

        uint32_t ua[2][4][4], ub[2][8][2];
        #pragma unroll
        for (int ks = 0; ks < 2; ks++) {
            uint32_t ka = aB + ks * 32;
            #pragma unroll
            for (int mt = 0; mt < 4; mt++)
                ldsm_x4(ua[ks][mt][0], ua[ks][mt][1], ua[ks][mt][2], ua[ks][mt][3],
                        ka + mt * (16 * AHS * 2));
            #pragma unroll
            for (int j = 0; j < 4; j++) {
                uint32_t addr = bhB + (uint32_t)(((ks * 16 + bk) * BHS + wn + bn + j * 16) * 2);
                ldsm_x4_t(ub[ks][2*j][0], ub[ks][2*j][1], ub[ks][2*j+1][0], ub[ks][2*j+1][1],
                          addr);
            }
        }
        #pragma unroll
        for (int ks = 0; ks < 2; ks++)
            #pragma unroll
            for (int mt = 0; mt < 4; mt++)
                #pragma unroll
                for (int nt = 0; nt < 8; nt++)
                    mma_f16(acc[mt][nt], ua[ks][mt], ub[ks][nt]);
        __syncthreads();
    }

    // ---------------- epilogue ----------------
    #pragma unroll
    for (int mt = 0; mt < 4; mt++) {
        #pragma unroll
        for (int h = 0; h < 2; h++) {
            int rl = wm + mt * 16 + g + h * 8;
            int gr = crow + rl;
            if (mode == 0) {
                size_t rbase = (size_t)gr * N;
                #pragma unroll
                for (int nt = 0; nt < 8; nt++) {
                    int c = ccol + wn + nt * 8 + tig * 2;
                    float v0 = acc[mt][nt][h * 2 + 0];
                    float v1 = acc[mt][nt][h * 2 + 1];
                    if (D) {
                        float2 dv = *(const float2*)(D + rbase + c);
                        v0 += dv.x; v1 += dv.y;
                    }
                    *(float2*)(C + rbase + c) = make_float2(v0, v1);
                }
            } else if (mode == 1) {
                if (gr < cnt) {
                    int slot = off + gr;
                    float s = g_tok_scale[g_slot_tok[slot]];
                    size_t rbase = (size_t)slot * N;
                    #pragma unroll
                    for (int nt = 0; nt < 8; nt++) {
                        int c = ccol + wn + nt * 8 + tig * 2;
                        *(float2*)(C + rbase + c) =
                            make_float2(s * acc[mt][nt][h * 2 + 0],
                                        s * acc[mt][nt][h * 2 + 1]);
                    }
                }
            } else {
                if (gr < cnt) {
                    int tok = g_slot_tok[off + gr];
                    size_t rbase = (size_t)tok * N;
                    #pragma unroll
                    for (int nt = 0; nt < 8; nt++) {
                        int c = ccol + wn + nt * 8 + tig * 2;
                        float2* cp = (float2*)(C + rbase + c);
                        float2 cv = *cp;
                        cv.x += acc[mt][nt][h * 2 + 0];
                        cv.y += acc[mt][nt][h * 2 + 1];
                        *cp = cv;
                    }
                }
            }
        }
    }
}

// ---------------- RoPE + L2-norm for q & k -> fp16 ----------------
__global__ void rope_l2_kernel(const float* __restrict__ qkv,
                               const float* __restrict__ freqs,
                               __half* __restrict__ qout,
                               __half* __restrict__ kout)
{
    int t = blockIdx.x;
    int lane = threadIdx.x & 31, w = threadIdx.x >> 5;
    int hh = blockIdx.y * 4 + w;
    int s = t & (SEQ - 1);

    const float* src;
    __half* dst;
    if (hh < NH) {
        src = qkv + (size_t)t * QKVW + hh * HD;
        dst = qout + (size_t)t * NH * HD + hh * HD;
    } else {
        int kv = hh - NH;
        src = qkv + (size_t)t * QKVW + NH * HD + kv * HD;
        dst = kout + (size_t)t * NKV * HD + kv * HD;
    }
    float4 xv = *(const float4*)(src + lane * 4);
    float4 fv = *(const float4*)(freqs + (size_t)s * HD + lane * 4);
    float o0 = xv.x * fv.x - xv.y * fv.y;
    float o1 = xv.x * fv.y + xv.y * fv.x;
    float o2 = xv.z * fv.z - xv.w * fv.w;
    float o3 = xv.z * fv.w + xv.w * fv.z;
    float ss = o0*o0 + o1*o1 + o2*o2 + o3*o3;
    #pragma unroll
    for (int o = 16; o; o >>= 1) ss += __shfl_xor_sync(0xffffffffu, ss, o);
    float r = rsqrtf(ss / (float)HD + EPS_L2);
    __half2 p0 = __floats2half2_rn(o0 * r, o1 * r);
    __half2 p1 = __floats2half2_rn(o2 * r, o3 * r);
    *(__half2*)(dst + lane * 4)     = p0;
    *(__half2*)(dst + lane * 4 + 2) = p1;
}

// =====================================================================
// flash attention: fp16 S-path (Q,K fp16 mma), tf32 P@V. 64 q rows/block.
// blockIdx.y reversed so longest tiles launch first (causal balance).
// =====================================================================
#define KH_STRIDE 136   // halves
#define VS_STRIDE 136   // floats
#define P_STRIDE  68    // floats
#define FA_SMEM   (64*KH_STRIDE*2 + 64*VS_STRIDE*4 + 64*P_STRIDE*4)

__global__ __launch_bounds__(128)
void flash_attn_kernel(const __half* __restrict__ q,
                       const __half* __restrict__ k,
                       const float* __restrict__ qkv,
                       __half* __restrict__ o)
{
    extern __shared__ char fsm[];
    __half* Ks = (__half*)fsm;                         // [64][KH_STRIDE]
    float*  Vs = (float*)(fsm + 64 * KH_STRIDE * 2);   // [64][VS_STRIDE]
    float*  Ps = Vs + 64 * VS_STRIDE;                  // [64][P_STRIDE]

    int bh = blockIdx.x;
    int b = bh >> 4, h = bh & 15;
    int kvh = h >> 2;
    int qt = gridDim.y - 1 - blockIdx.y;   // longest first
    int q0 = qt * 64;

    int tid = threadIdx.x, warp = tid >> 5, lane = tid & 31;
    int g = lane >> 2, tig = lane & 3;

    int qr0 = q0 + warp * 16 + g;
    int qr1 = qr0 + 8;
    const __half* qb0 = q + ((size_t)(b * SEQ + qr0) * NH + h) * HD;
    const __half* qb1 = q + ((size_t)(b * SEQ + qr1) * NH + h) * HD;
    uint32_t qa[8][4];
    #pragma unroll
    for (int ks = 0; ks < 8; ks++) {
        int c = ks * 16 + tig * 2;
        qa[ks][0] = *(const uint32_t*)&qb0[c];
        qa[ks][1] = *(const uint32_t*)&qb1[c];
        qa[ks][2] = *(const uint32_t*)&qb0[c + 8];
        qa[ks][3] = *(const uint32_t*)&qb1[c + 8];
    }

    float oacc[16][4];
    #pragma unroll
    for (int dt = 0; dt < 16; dt++)
        #pragma unroll
        for (int r = 0; r < 4; r++) oacc[dt][r] = 0.f;
    float m0 = -1e30f, m1 = -1e30f, l0 = 0.f, l1 = 0.f;

    uint32_t ksb = (uint32_t)__cvta_generic_to_shared(Ks);
    uint32_t vsb = (uint32_t)__cvta_generic_to_shared(Vs);

    const int ktiles = qt + 1;
    for (int kt = 0; kt < ktiles; kt++) {
        const __half* kptr = k + ((size_t)(b * SEQ + kt * 64) * NKV + kvh) * HD;
        const float*  vptr = qkv + (size_t)(b * SEQ + kt * 64) * QKVW + (NH + NKV) * HD + kvh * HD;
        #pragma unroll
        for (int it = 0; it < 8; it++) {
            int idx = tid + it * 128;
            int r = idx >> 4, c = (idx & 15) * 8;
            cp16(ksb + (uint32_t)(r * KH_STRIDE + c) * 2, kptr + (size_t)r * (NKV * HD) + c);
        }
        #pragma unroll
        for (int it = 0; it < 16; it++) {
            int idx = tid + it * 128;
            int r = idx >> 5, c = (idx & 31) * 4;
            cp16(vsb + (uint32_t)(r * VS_STRIDE + c) * 4, vptr + (size_t)r * QKVW + c);
        }
        asm volatile("cp.async.commit_group;");
        asm volatile("cp.async.wait_group 0;");
        __syncthreads();

        float sacc[8][4];
        #pragma unroll
        for (int nt = 0; nt < 8; nt++)
            #pragma unroll
            for (int r = 0; r < 4; r++) sacc[nt][r] = 0.f;

        #pragma unroll
        for (int ks = 0; ks < 8; ks++) {
            int kb = ks * 16 + tig * 2;
            uint32_t ub[8][2];
            #pragma unroll
            for (int nt = 0; nt < 8; nt++) {
                int kr = nt * 8 + g;
                ub[nt][0] = *(const uint32_t*)&Ks[kr * KH_STRIDE + kb];
                ub[nt][1] = *(const uint32_t*)&Ks[kr * KH_STRIDE + kb + 8];
            }
            #pragma unroll
            for (int nt = 0; nt < 8; nt++)
                mma_f16(sacc[nt], qa[ks], ub[nt]);
        }

        bool diag = (kt == ktiles - 1);
        float rmax0 = -1e30f, rmax1 = -1e30f;
        #pragma unroll
        for (int nt = 0; nt < 8; nt++) {
            int c0 = kt * 64 + nt * 8 + tig * 2;
            float s0 = sacc[nt][0] * SCALE;
            float s1 = sacc[nt][1] * SCALE;
            float s2 = sacc[nt][2] * SCALE;
            float s3 = sacc[nt][3] * SCALE;
            if (diag) {
                if (c0 > qr0)     s0 = -1e30f;
                if (c0 + 1 > qr0) s1 = -1e30f;
                if (c0 > qr1)     s2 = -1e30f;
                if (c0 + 1 > qr1) s3 = -1e30f;
            }
            sacc[nt][0] = s0; sacc[nt][1] = s1;
            sacc[nt][2] = s2; sacc[nt][3] = s3;
            rmax0 = fmaxf(rmax0, fmaxf(s0, s1));
            rmax1 = fmaxf(rmax1, fmaxf(s2, s3));
        }
        #pragma unroll
        for (int off = 1; off <= 2; off <<= 1) {
            rmax0 = fmaxf(rmax0, __shfl_xor_sync(0xffffffffu, rmax0, off));
            rmax1 = fmaxf(rmax1, __shfl_xor_sync(0xffffffffu, rmax1, off));
        }
        float mn0 = fmaxf(m0, rmax0);
        float mn1 = fmaxf(m1, rmax1);
        float corr0 = __expf(m0 - mn0);
        float corr1 = __expf(m1 - mn1);
        m0 = mn0; m1 = mn1;

        float psum0 = 0.f, psum1 = 0.f;
        #pragma unroll
        for (int nt = 0; nt < 8; nt++) {
            float p0 = __expf(sacc[nt][0] - mn0);
            float p1 = __expf(sacc[nt][1] - mn0);
            float p2 = __expf(sacc[nt][2] - mn1);
            float p3 = __expf(sacc[nt][3] - mn1);
            psum0 += p0 + p1;
            psum1 += p2 + p3;
            int c = nt * 8 + tig * 2;
            *(float2*)&Ps[(warp * 16 + g) * P_STRIDE + c]     = make_float2(p0, p1);
            *(float2*)&Ps[(warp * 16 + g + 8) * P_STRIDE + c] = make_float2(p2, p3);
        }
        #pragma unroll
        for (int off = 1; off <= 2; off <<= 1) {
            psum0 += __shfl_xor_sync(0xffffffffu, psum0, off);
            psum1 += __shfl_xor_sync(0xffffffffu, psum1, off);
        }
        l0 = l0 * corr0 + psum0;
        l1 = l1 * corr1 + psum1;

        #pragma unroll
        for (int dt = 0; dt < 16; dt++) {
            oacc[dt][0] *= corr0; oacc[dt][1] *= corr0;
            oacc[dt][2] *= corr1; oacc[dt][3] *= corr1;
        }
        __syncwarp();

        #pragma unroll
        for (int ks = 0; ks < 8; ks++) {
            int k8 = ks * 8;
            uint32_t pa[4];
            pa[0] = f2tf32(Ps[(warp * 16 + g) * P_STRIDE + k8 + tig]);
            pa[1] = f2tf32(Ps[(warp * 16 + g + 8) * P_STRIDE + k8 + tig]);
            pa[2] = f2tf32(Ps[(warp * 16 + g) * P_STRIDE + k8 + tig + 4]);
            pa[3] = f2tf32(Ps[(warp * 16 + g + 8) * P_STRIDE + k8 + tig + 4]);
            #pragma unroll
            for (int dt = 0; dt < 16; dt++) {
                uint32_t vb[2];
                vb[0] = f2tf32(Vs[(k8 + tig) * VS_STRIDE + dt * 8 + g]);
                vb[1] = f2tf32(Vs[(k8 + tig + 4) * VS_STRIDE + dt * 8 + g]);
                mma_tf32(oacc[dt], pa, vb);
            }
        }
        __syncthreads();
    }

    float inv0 = 1.f / l0, inv1 = 1.f / l1;
    __half* ob0 = o + ((size_t)(b * SEQ + qr0) * NH + h) * HD;
    __half* ob1 = o + ((size_t)(b * SEQ + qr1) * NH + h) * HD;
    #pragma unroll
    for (int dt = 0; dt < 16; dt++) {
        int d = dt * 8 + tig * 2;
        *(__half2*)(ob0 + d) = __floats2half2_rn(oacc[dt][0] * inv0, oacc[dt][1] * inv0);
        *(__half2*)(ob1 + d) = __floats2half2_rn(oacc[dt][2] * inv1, oacc[dt][3] * inv1);
    }
}

// ---------------- router ----------------
__global__ void zero_cnt_kernel()
{
    if (threadIdx.x < NEXP) g_cnt[threadIdx.x] = 0;
}

__global__ void router_kernel(const float* __restrict__ h2,
                              const float* __restrict__ wr)
{
    int t = blockIdx.x;
    const float* hrow = h2 + (size_t)t * HDIM;
    float l[NEXP];
    #pragma unroll
    for (int e = 0; e < NEXP; e++) l[e] = 0.f;
    for (int kk = threadIdx.x; kk < HDIM; kk += blockDim.x) {
        float hv = hrow[kk];
        const float* wrow = wr + (size_t)kk * NEXP;
        #pragma unroll
        for (int e = 0; e < NEXP; e++) l[e] += hv * wrow[e];
    }
    __shared__ float sums[NEXP];
    if (threadIdx.x < NEXP) sums[threadIdx.x] = 0.f;
    __syncthreads();
    #pragma unroll
    for (int e = 0; e < NEXP; e++) {
        float v = l[e];
        #pragma unroll
        for (int o = 16; o; o >>= 1) v += __shfl_xor_sync(0xffffffffu, v, o);
        if ((threadIdx.x & 31) == 0) atomicAdd(&sums[e], v);
    }
    __syncthreads();
    if (threadIdx.x == 0) {
        int best = 0;
        float bv = sums[0];
        #pragma unroll
        for (int e = 1; e < NEXP; e++)
            if (sums[e] > bv) { bv = sums[e]; best = e; }
        g_tok_expert[t] = best;
        g_tok_scale[t]  = 1.f / (1.f + __expf(-bv));
        g_tok_rank[t]   = atomicAdd(&g_cnt[best], 1);
    }
}

__global__ void offsets_kernel()
{
    if (threadIdx.x == 0) {
        int run = 0;
        for (int e = 0; e < NEXP; e++) { g_off[e] = run; run += g_cnt[e]; }
    }
}

__global__ void slot_kernel()
{
    int t = blockIdx.x * blockDim.x + threadIdx.x;
    if (t < TTOK)
        g_slot_tok[g_off[g_tok_expert[t]] + g_tok_rank[t]] = t;
}

// ---------------- SiLU(g)*u -> fp16 ----------------
__global__ void silu_mul_kernel(const float* __restrict__ gu,
                                __half* __restrict__ out)
{
    int i = blockIdx.x * blockDim.x + threadIdx.x;
    if (i >= TTOK * IDIM) return;
    int row = i / IDIM, col = i - row * IDIM;
    float g = gu[(size_t)row * 2 * IDIM + col];
    float u = gu[(size_t)row * 2 * IDIM + IDIM + col];
    float sg = 1.f / (1.f + __expf(-g));
    out[i] = __float2half(u * g * sg);
}

// ---------------- launch ----------------
extern "C" void kernel_launch(void* const* d_in, const int* in_sizes, int n_in,
                              void* d_out, int out_size)
{
    const float* hidden   = (const float*)d_in[0];
    const float* freqs    = (const float*)d_in[1];
    const float* w_ln1    = (const float*)d_in[2];
    const float* w_qkv    = (const float*)d_in[3];
    const float* w_o      = (const float*)d_in[4];
    const float* w_ln2    = (const float*)d_in[5];
    const float* w_router = (const float*)d_in[6];
    const float* w_gu_e   = (const float*)d_in[7];
    const float* w_down_e = (const float*)d_in[8];
    const float* w_sh_gu  = (const float*)d_in[9];
    const float* w_sh_dn  = (const float*)d_in[10];
    float* out = (float*)d_out;

    float *p_qkv, *p_x2, *p_h2, *p_gus, *p_gur;
    __half *p_h16, *p_q16, *p_k16, *p_o16, *p_h2_16, *p_acs16, *p_acr16;
    __half *p_wqkv16, *p_wo16, *p_wshgu16, *p_wshdn16, *p_wgu16, *p_wdn16;
    cudaGetSymbolAddress((void**)&p_qkv,   g_qkv);
    cudaGetSymbolAddress((void**)&p_x2,    g_x2);
    cudaGetSymbolAddress((void**)&p_h2,    g_h2);
    cudaGetSymbolAddress((void**)&p_gus,   g_gus);
    cudaGetSymbolAddress((void**)&p_gur,   g_gur);
    cudaGetSymbolAddress((void**)&p_h16,   g_h16);
    cudaGetSymbolAddress((void**)&p_q16,   g_q16);
    cudaGetSymbolAddress((void**)&p_k16,   g_k16);
    cudaGetSymbolAddress((void**)&p_o16,   g_o16);
    cudaGetSymbolAddress((void**)&p_h2_16, g_h2_16);
    cudaGetSymbolAddress((void**)&p_acs16, g_acs16);
    cudaGetSymbolAddress((void**)&p_acr16, g_acr16);
    cudaGetSymbolAddress((void**)&p_wqkv16, g_wqkv16);
    cudaGetSymbolAddress((void**)&p_wo16,   g_wo16);
    cudaGetSymbolAddress((void**)&p_wshgu16,g_wshgu16);
    cudaGetSymbolAddress((void**)&p_wshdn16,g_wshdn16);
    cudaGetSymbolAddress((void**)&p_wgu16,  g_wgu16);
    cudaGetSymbolAddress((void**)&p_wdn16,  g_wdn16);

    static int attr_set = 0;
    if (!attr_set) {
        cudaFuncSetAttribute(flash_attn_kernel,
                             cudaFuncAttributeMaxDynamicSharedMemorySize, FA_SMEM);
        cudaFuncSetAttribute(hgemm,
                             cudaFuncAttributeMaxDynamicSharedMemorySize, HG_SMEM);
        attr_set = 1;
    }

    // 0. weight convert fp32 -> fp16 (same layout, fully coalesced)
    {
        size_t n;
        n = (size_t)HDIM * QKVW;
        cvt_kernel<<<(unsigned)((n/8 + 255)/256), 256>>>(w_qkv, p_wqkv16, n);
        n = (size_t)NH * HD * HDIM;
        cvt_kernel<<<(unsigned)((n/8 + 255)/256), 256>>>(w_o, p_wo16, n);
        n = (size_t)HDIM * 2 * IDIM;
        cvt_kernel<<<(unsigned)((n/8 + 255)/256), 256>>>(w_sh_gu, p_wshgu16, n);
        n = (size_t)IDIM * HDIM;
        cvt_kernel<<<(unsigned)((n/8 + 255)/256), 256>>>(w_sh_dn, p_wshdn16, n);
        n = (size_t)NEXP * HDIM * 2 * IDIM;
        cvt_kernel<<<(unsigned)((n/8 + 255)/256), 256>>>(w_gu_e, p_wgu16, n);
        n = (size_t)NEXP * IDIM * HDIM;
        cvt_kernel<<<(unsigned)((n/8 + 255)/256), 256>>>(w_down_e, p_wdn16, n);
    }

    // 1. rmsnorm1 -> fp16
    rmsnorm_kernel<<<TTOK, 256>>>(hidden, w_ln1, p_h16, nullptr);
    // 2. qkv = h @ w_qkv
    hgemm<<<dim3(QKVW/128, TTOK/128), 128, HG_SMEM>>>(TTOK, QKVW, HDIM, p_h16, p_wqkv16, 0, p_qkv, nullptr, 0);
    // 3. rope + l2 norm -> fp16 q/k
    rope_l2_kernel<<<dim3(TTOK, 5), 128>>>(p_qkv, freqs, p_q16, p_k16);
    // 4. flash attention -> fp16 O
    flash_attn_kernel<<<dim3(BATCH*NH, SEQ/64), 128, FA_SMEM>>>(p_q16, p_k16, p_qkv, p_o16);
    // 5. x2 = hidden + o @ w_o
    hgemm<<<dim3(HDIM/128, TTOK/128), 128, HG_SMEM>>>(TTOK, HDIM, NH*HD, p_o16, p_wo16, 0, p_x2, hidden, 0);
    // 6. rmsnorm2 -> fp16 + fp32
    rmsnorm_kernel<<<TTOK, 256>>>(p_x2, w_ln2, p_h2_16, p_h2);
    // 7. router (fp32 logits)
    zero_cnt_kernel<<<1, 32>>>();
    router_kernel<<<TTOK, 256>>>(p_h2, w_router);
    offsets_kernel<<<1, 32>>>();
    slot_kernel<<<TTOK/256, 256>>>();
    // 8. shared expert
    hgemm<<<dim3(2*IDIM/128, TTOK/128), 128, HG_SMEM>>>(TTOK, 2*IDIM, HDIM, p_h2_16, p_wshgu16, 0, p_gus, nullptr, 0);
    silu_mul_kernel<<<(TTOK*IDIM + 255)/256, 256>>>(p_gus, p_acs16);
    hgemm<<<dim3(HDIM/128, TTOK/128), 128, HG_SMEM>>>(TTOK, HDIM, IDIM, p_acs16, p_wshdn16, 0, out, p_x2, 0);
    // 9. routed experts (top-1, gathered)
    hgemm<<<dim3(2*IDIM/128, TTOK/128, NEXP), 128, HG_SMEM>>>(TTOK, 2*IDIM, HDIM, p_h2_16, p_wgu16,
                                                              (size_t)HDIM*2*IDIM, p_gur, nullptr, 1);
    silu_mul_kernel<<<(TTOK*IDIM + 255)/256, 256>>>(p_gur, p_acr16);
    hgemm<<<dim3(HDIM/128, TTOK/128, NEXP), 128, HG_SMEM>>>(TTOK, HDIM, IDIM, p_acr16, p_wdn16,
                                                            (size_t)IDIM*HDIM, out, nullptr, 2);
}